// round 16
// baseline (speedup 1.0000x reference)
#include <cuda_runtime.h>
#include <cuda_fp16.h>
#include <cstdint>

#define TT    256
#define BATCH 1024
#define LATD  128
#define OUTD  64
#define HB    (BATCH * 256)

// SMEM layout (bytes)
#define SM_WF 0          // 98304: B-fragments fp16 uint4-paired: [6 ch][8 ks][4 p][32 lane]
#define SM_P  98304      // 65536: A tile P (h0), 2 chunks x 32768, 256B stride XOR-swizzled
#define SM_Q  163840     // 65536: A tile Q (h1)
#define SMEM_SZ 229376

// ---------------- static device scratch (no allocations) ----------------
__device__ uint32_t g_wf[393216];                    // [ntile][ch][ks][p][lane] uint4-packed
__device__ uint2 g_wof[16 * 2 * 8 * 32];             // out-proj fragments [nt][ch][ks][lane]
__device__ float g_b1p[1024];                        // permuted bias1
__device__ float g_gx0p[BATCH * 1024];               // [b][permuted col]
__device__ float g_cinit[BATCH * 512];               // [b][layer*256+unit]
__device__ __half g_h0f[2 * HB], g_h1f[2 * HB];      // double-buffered fp16 h
__device__ unsigned g_barm[8];                       // per-mtile barrier counters

// ---------------- helpers ----------------
__device__ __forceinline__ uint32_t s2u(const void* p) {
    uint32_t a;
    asm("{ .reg .u64 t; cvta.to.shared.u64 t, %1; cvt.u32.u64 %0, t; }" : "=r"(a) : "l"(p));
    return a;
}
__device__ __forceinline__ void stg16(__half* p, __half v) {
    unsigned short u = *(unsigned short*)&v;
    asm volatile("st.global.cg.u16 [%0], %1;" :: "l"(p), "h"(u) : "memory");
}
__device__ __forceinline__ void cpa16(uint32_t saddr, const void* gptr) {
    asm volatile("cp.async.cg.shared.global [%0], [%1], 16;" :: "r"(saddr), "l"(gptr) : "memory");
}
#define CP_COMMIT() asm volatile("cp.async.commit_group;" ::: "memory")
#define CP_WAIT0()  asm volatile("cp.async.wait_group 0;" ::: "memory")
#define CP_WAIT1()  asm volatile("cp.async.wait_group 1;" ::: "memory")

__device__ __forceinline__ float sigf(float x) { return __fdividef(1.f, 1.f + __expf(-x)); }
__device__ __forceinline__ float tanhf_(float x) {
    x = fminf(fmaxf(x, -15.f), 15.f);
    float e = __expf(2.f * x);
    return __fdividef(e - 1.f, e + 1.f);
}
// permuted column -> original gate row. col c of a CTA: gate=(c>>5)*2+(c&1),
// unit_local = ((c>>3)&3)*4 + ((c>>1)&3)
__device__ __forceinline__ int col2row(int ntile, int c) {
    int g = (c >> 5) * 2 + (c & 1);
    int u = ((c >> 3) & 3) * 4 + ((c >> 1) & 3);
    return g * 256 + ntile * 16 + u;
}

// ================= prep kernels =================
// B fragments, n8k16 per-lane layout: lane holds b[k,n], n = nt*8 + (lane>>2),
// k = (lane&3)*2 + j + e*8. Packed as uint4 per nt-pair p = nt>>1:
// uint32 index = base + (ks*4+p)*128 + lane*4 + (nt&1)*2 + e.
__global__ void prep_wfrag(const float* __restrict__ w_hh0,
                           const float* __restrict__ w_ih1,
                           const float* __restrict__ w_hh1) {
    int gid = blockIdx.x * 256 + threadIdx.x;        // 393216
    int ntile = gid / 24576;
    int rem   = gid % 24576;
    int chunk = rem >> 12;                           // 0,1:L0  2..5:L1
    int r2    = rem & 4095;
    int ks    = r2 >> 9;
    int nt    = (r2 >> 6) & 7;
    int lane  = (r2 >> 1) & 31;
    int e     = r2 & 1;
    int c     = nt * 8 + (lane >> 2);
    int srow  = col2row(ntile, c);
    int kb    = (chunk < 2) ? chunk * 128 : (chunk - 2) * 128;
    uint32_t w = 0;
    #pragma unroll
    for (int j = 0; j < 2; j++) {
        int kg = kb + ks * 16 + (lane & 3) * 2 + j + e * 8;
        float v;
        if (chunk < 2) v = w_hh0[srow * 256 + kg];
        else v = (kg < 256) ? w_ih1[srow * 256 + kg] : w_hh1[srow * 256 + kg - 256];
        __half h = __float2half_rn(v);
        w |= (uint32_t)(*(uint16_t*)&h) << (16 * j);
    }
    int dst = ntile * 24576 + chunk * 4096 + (ks * 4 + (nt >> 1)) * 128
            + lane * 4 + (nt & 1) * 2 + e;
    g_wf[dst] = w;
}

__global__ void prep_misc(const float* __restrict__ w_out,
                          const float* __restrict__ b_ih1,
                          const float* __restrict__ b_hh1) {
    int idx = blockIdx.x * 256 + threadIdx.x;        // 16384
    // out-proj fragments: [nt][ch][ks][lane]; lane holds b[k,n], n=lane>>2 (n<4 real)
    if (idx < 8192) {
        int lane = idx & 31, ks = (idx >> 5) & 7, ch = (idx >> 8) & 1, nt = idx >> 9;
        int n = lane >> 2;
        uint2 w = make_uint2(0u, 0u);
        if (n < 4) {
            int col = nt * 4 + n;
            uint32_t pk[2];
            #pragma unroll
            for (int e = 0; e < 2; e++) {
                uint32_t v = 0;
                #pragma unroll
                for (int j = 0; j < 2; j++) {
                    int k = ch * 128 + ks * 16 + (lane & 3) * 2 + j + e * 8;
                    __half h = __float2half_rn(w_out[col * 256 + k]);
                    v |= (uint32_t)(*(uint16_t*)&h) << (16 * j);
                }
                pk[e] = v;
            }
            w = make_uint2(pk[0], pk[1]);
        }
        g_wof[idx] = w;
    }
    if (idx < 1024) {
        int ntile = idx >> 6, c = idx & 63;
        int srow = col2row(ntile, c);
        g_b1p[idx] = b_ih1[srow] + b_hh1[srow];
    }
    if (idx < 8) g_barm[idx] = 0;
}

__global__ void prep_init(const float* __restrict__ latent,
                          const float* __restrict__ w_lh, const float* __restrict__ b_lh,
                          const float* __restrict__ w_lc, const float* __restrict__ b_lc,
                          const float* __restrict__ w_ih0, const float* __restrict__ b_ih0,
                          const float* __restrict__ b_hh0) {
    __shared__ float lat[LATD];
    const int b = blockIdx.x, t = threadIdx.x;
    if (t < LATD) lat[t] = latent[b * LATD + t];
    __syncthreads();

    #pragma unroll
    for (int g = 0; g < 4; g++) {
        int n = g * 256 + t;
        const float4* wr = (const float4*)(w_ih0 + n * LATD);
        float acc = b_ih0[n] + b_hh0[n];
        #pragma unroll 8
        for (int q = 0; q < LATD / 4; q++) {
            float4 w4 = __ldg(wr + q);
            acc += lat[4*q]*w4.x + lat[4*q+1]*w4.y + lat[4*q+2]*w4.z + lat[4*q+3]*w4.w;
        }
        // permuted col: unit t, gate g
        int colp = (t >> 4) * 64 + (g >> 1) * 32 + ((t >> 2) & 3) * 8 + (t & 3) * 2 + (g & 1);
        g_gx0p[b * 1024 + colp] = acc;
    }
    #pragma unroll
    for (int half = 0; half < 2; half++) {
        float hv, cv;
        {
            const float4* wr = (const float4*)(w_lh + (half * 256 + t) * LATD);
            float acc = b_lh[half * 256 + t];
            #pragma unroll 8
            for (int q = 0; q < LATD / 4; q++) {
                float4 w4 = __ldg(wr + q);
                acc += lat[4*q]*w4.x + lat[4*q+1]*w4.y + lat[4*q+2]*w4.z + lat[4*q+3]*w4.w;
            }
            hv = acc;
        }
        {
            const float4* wr = (const float4*)(w_lc + (half * 256 + t) * LATD);
            float acc = b_lc[half * 256 + t];
            #pragma unroll 8
            for (int q = 0; q < LATD / 4; q++) {
                float4 w4 = __ldg(wr + q);
                acc += lat[4*q]*w4.x + lat[4*q+1]*w4.y + lat[4*q+2]*w4.z + lat[4*q+3]*w4.w;
            }
            cv = acc;
        }
        int p = HB + b * 256 + t;                    // initial h -> buffer 1
        if (half == 0) g_h0f[p] = __float2half_rn(hv);
        else           g_h1f[p] = __float2half_rn(hv);
        g_cinit[b * 512 + half * 256 + t] = cv;
    }
}

// ================= main kernel pieces =================
// per-mtile barrier: 16 CTAs per group
__device__ __forceinline__ void gbarm(int tid, int mtile, unsigned target) {
    __threadfence();
    __syncthreads();
    if (tid == 0) {
        atomicAdd(&g_barm[mtile], 1u);
        unsigned v;
        do {
            asm volatile("ld.acquire.gpu.global.u32 %0, [%1];" : "=r"(v) : "l"(&g_barm[mtile]) : "memory");
        } while (v < target);
    }
    __syncthreads();
}

// async-copy one 128x128 fp16 chunk into XOR-swizzled 256B-stride A tile (512 thr)
__device__ __forceinline__ void fill_async(uint32_t sdst, const __half* src, int kofs, int tid) {
    const uint4* s4 = (const uint4*)(src + kofs);    // row stride 512B = 32 uint4
    #pragma unroll
    for (int it = 0; it < 4; it++) {
        int i = tid + it * 512;
        int r = i >> 4, seg = i & 15;
        cpa16(sdst + r * 256 + ((seg ^ (r & 7)) << 4), s4 + r * 32 + seg);
    }
}

// GEMM pass over a K=128 chunk: warp = 16 rows x 32 cols (nt pairs wn, wn+2)
__device__ __forceinline__ void gemm_pass(uint32_t at_warp, uint32_t wf, float acc[4][4],
                                          int lane, int wn) {
    #pragma unroll
    for (int ks = 0; ks < 8; ks++) {
        uint32_t a0, a1, a2, a3;
        uint32_t row = lane & 15;
        uint32_t seg = (uint32_t)(ks * 2) + (uint32_t)(lane >> 4);
        uint32_t aaddr = at_warp + row * 256 + ((seg ^ (row & 7)) << 4);
        asm volatile("ldmatrix.sync.aligned.m8n8.x4.shared.b16 {%0,%1,%2,%3}, [%4];"
                     : "=r"(a0), "=r"(a1), "=r"(a2), "=r"(a3) : "r"(aaddr));
        uint4 B0, B1;
        uint32_t b0a = wf + ((ks * 4 + wn) * 32 + lane) * 16;
        uint32_t b1a = wf + ((ks * 4 + wn + 2) * 32 + lane) * 16;
        asm volatile("ld.shared.v4.u32 {%0,%1,%2,%3}, [%4];"
                     : "=r"(B0.x), "=r"(B0.y), "=r"(B0.z), "=r"(B0.w) : "r"(b0a));
        asm volatile("ld.shared.v4.u32 {%0,%1,%2,%3}, [%4];"
                     : "=r"(B1.x), "=r"(B1.y), "=r"(B1.z), "=r"(B1.w) : "r"(b1a));
        asm volatile("mma.sync.aligned.m16n8k16.row.col.f32.f16.f16.f32 "
            "{%0,%1,%2,%3}, {%4,%5,%6,%7}, {%8,%9}, {%0,%1,%2,%3};"
            : "+f"(acc[0][0]), "+f"(acc[0][1]), "+f"(acc[0][2]), "+f"(acc[0][3])
            : "r"(a0), "r"(a1), "r"(a2), "r"(a3), "r"(B0.x), "r"(B0.y));
        asm volatile("mma.sync.aligned.m16n8k16.row.col.f32.f16.f16.f32 "
            "{%0,%1,%2,%3}, {%4,%5,%6,%7}, {%8,%9}, {%0,%1,%2,%3};"
            : "+f"(acc[1][0]), "+f"(acc[1][1]), "+f"(acc[1][2]), "+f"(acc[1][3])
            : "r"(a0), "r"(a1), "r"(a2), "r"(a3), "r"(B0.z), "r"(B0.w));
        asm volatile("mma.sync.aligned.m16n8k16.row.col.f32.f16.f16.f32 "
            "{%0,%1,%2,%3}, {%4,%5,%6,%7}, {%8,%9}, {%0,%1,%2,%3};"
            : "+f"(acc[2][0]), "+f"(acc[2][1]), "+f"(acc[2][2]), "+f"(acc[2][3])
            : "r"(a0), "r"(a1), "r"(a2), "r"(a3), "r"(B1.x), "r"(B1.y));
        asm volatile("mma.sync.aligned.m16n8k16.row.col.f32.f16.f16.f32 "
            "{%0,%1,%2,%3}, {%4,%5,%6,%7}, {%8,%9}, {%0,%1,%2,%3};"
            : "+f"(acc[3][0]), "+f"(acc[3][1]), "+f"(acc[3][2]), "+f"(acc[3][3])
            : "r"(a0), "r"(a1), "r"(a2), "r"(a3), "r"(B1.z), "r"(B1.w));
    }
}

// out projection for this CTA's 4 cols from the Q tile (h1), warp's 16 rows
__device__ __forceinline__ void outproj(uint32_t Qw0, uint32_t Qw1, const uint2* wofp,
                                        float bo0, float bo1, float* __restrict__ out,
                                        int so, int rbase, int ntile, int lane) {
    float oa[4] = {0.f, 0.f, 0.f, 0.f};
    #pragma unroll
    for (int ch = 0; ch < 2; ch++) {
        uint32_t qb = ch ? Qw1 : Qw0;
        #pragma unroll
        for (int ks = 0; ks < 8; ks++) {
            uint32_t a0, a1, a2, a3;
            uint32_t row = lane & 15;
            uint32_t seg = (uint32_t)(ks * 2) + (uint32_t)(lane >> 4);
            uint32_t aaddr = qb + row * 256 + ((seg ^ (row & 7)) << 4);
            asm volatile("ldmatrix.sync.aligned.m8n8.x4.shared.b16 {%0,%1,%2,%3}, [%4];"
                         : "=r"(a0), "=r"(a1), "=r"(a2), "=r"(a3) : "r"(aaddr));
            uint2 bb = __ldg(wofp + ch * 256 + ks * 32);
            asm volatile(
                "mma.sync.aligned.m16n8k16.row.col.f32.f16.f16.f32 "
                "{%0,%1,%2,%3}, {%4,%5,%6,%7}, {%8,%9}, {%0,%1,%2,%3};"
                : "+f"(oa[0]), "+f"(oa[1]), "+f"(oa[2]), "+f"(oa[3])
                : "r"(a0), "r"(a1), "r"(a2), "r"(a3), "r"(bb.x), "r"(bb.y));
        }
    }
    if ((lane & 3) < 2) {
        int co = ntile * 4 + 2 * (lane & 3);
        float2 v0 = make_float2(oa[0] + bo0, oa[1] + bo1);
        float2 v1 = make_float2(oa[2] + bo0, oa[3] + bo1);
        *(float2*)&out[(rbase * TT + so) * OUTD + co] = v0;
        *(float2*)&out[((rbase + 8) * TT + so) * OUTD + co] = v1;
    }
}

// cell update: acc[j] j<2 -> gates i/f (nt=2wn+j), acc[2+j] -> g/o, same units
__device__ __forceinline__ void cell_pub(float acc[4][4], float* c,
                                         __half* gh, int rbase, int ntile, int wn, int lane) {
    #pragma unroll
    for (int j = 0; j < 2; j++) {
        #pragma unroll
        for (int rh = 0; rh < 2; rh++) {
            int i = j * 2 + rh;
            float gi = acc[j][rh * 2],     gf = acc[j][rh * 2 + 1];
            float gg = acc[2 + j][rh * 2], go = acc[2 + j][rh * 2 + 1];
            float cn = sigf(gf) * c[i] + sigf(gi) * tanhf_(gg);
            c[i] = cn;
            float h = sigf(go) * tanhf_(cn);
            int rowg = rbase + rh * 8;
            int ug = ntile * 16 + 8 * wn + 4 * j + (lane & 3);
            stg16(gh + rowg * 256 + ug, __float2half_rn(h));
        }
    }
}

__global__ void __launch_bounds__(512, 1)
lstm_mma(const float* __restrict__ b_out, float* __restrict__ out) {
    extern __shared__ char smem[];
    const int tid = threadIdx.x, wid = tid >> 5, lane = tid & 31;
    const int wm = wid >> 1, wn = wid & 1;
    const int mtile = blockIdx.x >> 4, ntile = blockIdx.x & 15;
    const uint32_t sbase = s2u(smem);
    const uint32_t P = sbase + SM_P, Q = sbase + SM_Q;
    const uint32_t Pw0 = P + wm * 4096, Pw1 = P + 32768 + wm * 4096;
    const uint32_t Qw0 = Q + wm * 4096, Qw1 = Q + 32768 + wm * 4096;
    const int rbase = mtile * 128 + wm * 16 + (lane >> 2);
    const int hoff = mtile * 128 * 256;

    // weight fragments -> SMEM
    {
        const uint4* sh = (const uint4*)(g_wf + ntile * 24576);
        uint4* dh = (uint4*)(smem + SM_WF);
        for (int i = tid; i < 6144; i += 512) dh[i] = __ldg(sh + i);
    }

    // per-lane constants; j<2 -> nt=2wn+j (i/f), j>=2 -> nt=2wn+4+(j-2) (g/o)
    float gx[4][4], b1r[4][2];
    #pragma unroll
    for (int j = 0; j < 4; j++) {
        int ntj = 2 * wn + ((j < 2) ? j : 4 + (j - 2));
        #pragma unroll
        for (int r = 0; r < 4; r++) {
            int rowg = rbase + (r >> 1) * 8;
            int c = ntj * 8 + 2 * (lane & 3) + (r & 1);
            gx[j][r] = __ldg(&g_gx0p[rowg * 1024 + ntile * 64 + c]);
        }
        b1r[j][0] = __ldg(&g_b1p[ntile * 64 + ntj * 8 + 2 * (lane & 3)]);
        b1r[j][1] = __ldg(&g_b1p[ntile * 64 + ntj * 8 + 2 * (lane & 3) + 1]);
    }
    float c0[4], c1[4];
    #pragma unroll
    for (int i = 0; i < 4; i++) {
        int j = i >> 1, rh = i & 1;
        int rowg = rbase + rh * 8;
        int ug = ntile * 16 + 8 * wn + 4 * j + (lane & 3);
        c0[j * 2 + rh] = __ldg(&g_cinit[rowg * 512 + ug]);
        c1[j * 2 + rh] = __ldg(&g_cinit[rowg * 512 + 256 + ug]);
    }
    float bo0 = 0.f, bo1 = 0.f;
    if ((lane & 3) < 2) {
        bo0 = __ldg(&b_out[ntile * 4 + 2 * (lane & 3)]);
        bo1 = __ldg(&b_out[ntile * 4 + 2 * (lane & 3) + 1]);
    }
    const uint2* wofp = g_wof + ntile * 512 + lane;
    __syncthreads();

    // pre-fill P with h0_init (buffer 1)
    fill_async(P,         g_h0f + HB + hoff, 0,   tid);
    fill_async(P + 32768, g_h0f + HB + hoff, 128, tid);
    CP_COMMIT();
    CP_WAIT0();
    __syncthreads();

    unsigned tgt = 16;
    float acc[4][4];

    #pragma unroll 1
    for (int s = 0; s < TT; s++) {
        const int wb = s & 1, rb = wb ^ 1;

        // prefetch Q <- h1_prev (overlaps layer-0 GEMM; P already resident)
        fill_async(Q,         g_h1f + rb * HB + hoff, 0,   tid);
        fill_async(Q + 32768, g_h1f + rb * HB + hoff, 128, tid);
        CP_COMMIT();

        // ---------------- layer 0 on resident P ----------------
        #pragma unroll
        for (int j = 0; j < 4; j++)
            #pragma unroll
            for (int r = 0; r < 4; r++) acc[j][r] = gx[j][r];
        gemm_pass(Pw0, sbase + SM_WF + 0 * 16384, acc, lane, wn);
        gemm_pass(Pw1, sbase + SM_WF + 1 * 16384, acc, lane, wn);

        cell_pub(acc, c0, g_h0f + wb * HB, rbase, ntile, wn, lane);

        gbarm(tid, mtile, tgt); tgt += 16;            // barrier A: h0_new visible

        // refill P <- h0_new (hidden under W1b + outproj below)
        fill_async(P,         g_h0f + wb * HB + hoff, 0,   tid);
        fill_async(P + 32768, g_h0f + wb * HB + hoff, 128, tid);
        CP_COMMIT();

        CP_WAIT1();                                   // Q done (P may still fly)
        __syncthreads();

        // ---------------- layer 1: h1_prev part on Q ----------------
        #pragma unroll
        for (int j = 0; j < 4; j++) {
            acc[j][0] = b1r[j][0]; acc[j][1] = b1r[j][1];
            acc[j][2] = b1r[j][0]; acc[j][3] = b1r[j][1];
        }
        gemm_pass(Qw0, sbase + SM_WF + 4 * 16384, acc, lane, wn);
        gemm_pass(Qw1, sbase + SM_WF + 5 * 16384, acc, lane, wn);

        // out projection for step s-1 (Q holds h1_new(s-1)); wn==0 warps cover all rows
        if (s > 0 && wn == 0)
            outproj(Qw0, Qw1, wofp, bo0, bo1, out, s - 1, rbase, ntile, lane);

        CP_WAIT0();                                   // P (h0_new) done
        __syncthreads();

        // ---------------- layer 1: h0_new part on P ----------------
        gemm_pass(Pw0, sbase + SM_WF + 2 * 16384, acc, lane, wn);
        gemm_pass(Pw1, sbase + SM_WF + 3 * 16384, acc, lane, wn);

        cell_pub(acc, c1, g_h1f + wb * HB, rbase, ntile, wn, lane);

        gbarm(tid, mtile, tgt); tgt += 16;            // barrier B: h1_new visible
    }

    // epilogue: out for step TT-1 (h1f buffer wb(TT-1) = 1)
    fill_async(Q,         g_h1f + HB + hoff, 0,   tid);
    fill_async(Q + 32768, g_h1f + HB + hoff, 128, tid);
    CP_COMMIT();
    CP_WAIT0();
    __syncthreads();
    if (wn == 0)
        outproj(Qw0, Qw1, wofp, bo0, bo1, out, TT - 1, rbase, ntile, lane);
}

// ================= launch =================
extern "C" void kernel_launch(void* const* d_in, const int* in_sizes, int n_in,
                              void* d_out, int out_size) {
    const float* latent = (const float*)d_in[0];
    const float* w_lh   = (const float*)d_in[1];
    const float* b_lh   = (const float*)d_in[2];
    const float* w_lc   = (const float*)d_in[3];
    const float* b_lc   = (const float*)d_in[4];
    const float* w_ih0  = (const float*)d_in[5];
    const float* w_hh0  = (const float*)d_in[6];
    const float* b_ih0  = (const float*)d_in[7];
    const float* b_hh0  = (const float*)d_in[8];
    const float* w_ih1  = (const float*)d_in[9];
    const float* w_hh1  = (const float*)d_in[10];
    const float* b_ih1  = (const float*)d_in[11];
    const float* b_hh1  = (const float*)d_in[12];
    const float* w_out  = (const float*)d_in[13];
    const float* b_out  = (const float*)d_in[14];
    float* out = (float*)d_out;

    cudaFuncSetAttribute(lstm_mma, cudaFuncAttributeMaxDynamicSharedMemorySize, SMEM_SZ);

    prep_wfrag<<<1536, 256>>>(w_hh0, w_ih1, w_hh1);
    prep_misc<<<64, 256>>>(w_out, b_ih1, b_hh1);
    prep_init<<<BATCH, 256>>>(latent, w_lh, b_lh, w_lc, b_lc, w_ih0, b_ih0, b_hh0);
    lstm_mma<<<128, 512, SMEM_SZ>>>(b_out, out);
}

// round 17
// speedup vs baseline: 1.2020x; 1.2020x over previous
#include <cuda_runtime.h>
#include <cuda_fp16.h>
#include <cstdint>

#define TT    256
#define BATCH 1024
#define LATD  128
#define OUTD  64
#define HB    (BATCH * 256)

// SMEM layout (bytes)
#define SM_WF 0          // 98304: B-fragments fp16, [6 ch][8 ks][8 nt][32 lane][2] uint32
#define SM_P  98304      // 65536: A tile P (h0(p-1)), 2 chunks x 32768, XOR-swizzled
#define SM_Q  163840     // 65536: A tile Q (h1(p-2))
#define SMEM_SZ 229376

// ---------------- static device scratch (no allocations) ----------------
__device__ uint32_t g_wf[393216];
__device__ uint2 g_wof[16 * 2 * 8 * 32];             // out-proj fragments [nt][ch][ks][lane]
__device__ float g_b1p[1024];                        // permuted bias1
__device__ float g_gx0p[BATCH * 1024];               // [b][permuted col]
__device__ float g_cinit[BATCH * 512];               // [b][layer*256+unit]
__device__ __half g_h0f[2 * HB], g_h1f[2 * HB];      // double-buffered fp16 h
__device__ unsigned g_barm[8];                       // per-mtile barrier counters

// ---------------- helpers ----------------
__device__ __forceinline__ uint32_t s2u(const void* p) {
    uint32_t a;
    asm("{ .reg .u64 t; cvta.to.shared.u64 t, %1; cvt.u32.u64 %0, t; }" : "=r"(a) : "l"(p));
    return a;
}
__device__ __forceinline__ void stg16(__half* p, __half v) {
    unsigned short u = *(unsigned short*)&v;
    asm volatile("st.global.cg.u16 [%0], %1;" :: "l"(p), "h"(u) : "memory");
}
__device__ __forceinline__ void cpa16(uint32_t saddr, const void* gptr) {
    asm volatile("cp.async.cg.shared.global [%0], [%1], 16;" :: "r"(saddr), "l"(gptr) : "memory");
}
#define CP_COMMIT() asm volatile("cp.async.commit_group;" ::: "memory")
#define CP_WAIT0()  asm volatile("cp.async.wait_group 0;" ::: "memory")
#define CP_WAIT1()  asm volatile("cp.async.wait_group 1;" ::: "memory")

__device__ __forceinline__ float sigf(float x) { return __fdividef(1.f, 1.f + __expf(-x)); }
__device__ __forceinline__ float tanhf_(float x) {
    x = fminf(fmaxf(x, -15.f), 15.f);
    float e = __expf(2.f * x);
    return __fdividef(e - 1.f, e + 1.f);
}
__device__ __forceinline__ int col2row(int ntile, int c) {
    int g = (c >> 5) * 2 + (c & 1);
    int u = ((c >> 3) & 3) * 4 + ((c >> 1) & 3);
    return g * 256 + ntile * 16 + u;
}

// ================= prep kernels (R15-identical layouts) =================
__global__ void prep_wfrag(const float* __restrict__ w_hh0,
                           const float* __restrict__ w_ih1,
                           const float* __restrict__ w_hh1) {
    int gid = blockIdx.x * 256 + threadIdx.x;        // 393216
    int ntile = gid / 24576;
    int rem   = gid % 24576;
    int chunk = rem >> 12;
    int r2    = rem & 4095;
    int ks    = r2 >> 9;
    int nt    = (r2 >> 6) & 7;
    int lane  = (r2 >> 1) & 31;
    int e     = r2 & 1;
    int c     = nt * 8 + (lane >> 2);
    int srow  = col2row(ntile, c);
    int kb    = (chunk < 2) ? chunk * 128 : (chunk - 2) * 128;
    uint32_t w = 0;
    #pragma unroll
    for (int j = 0; j < 2; j++) {
        int kg = kb + ks * 16 + (lane & 3) * 2 + j + e * 8;
        float v;
        if (chunk < 2) v = w_hh0[srow * 256 + kg];
        else v = (kg < 256) ? w_ih1[srow * 256 + kg] : w_hh1[srow * 256 + kg - 256];
        __half h = __float2half_rn(v);
        w |= (uint32_t)(*(uint16_t*)&h) << (16 * j);
    }
    g_wf[gid] = w;
}

__global__ void prep_misc(const float* __restrict__ w_out,
                          const float* __restrict__ b_ih1,
                          const float* __restrict__ b_hh1) {
    int idx = blockIdx.x * 256 + threadIdx.x;        // 16384
    if (idx < 8192) {
        int lane = idx & 31, ks = (idx >> 5) & 7, ch = (idx >> 8) & 1, nt = idx >> 9;
        int n = lane >> 2;
        uint2 w = make_uint2(0u, 0u);
        if (n < 4) {
            int col = nt * 4 + n;
            uint32_t pk[2];
            #pragma unroll
            for (int e = 0; e < 2; e++) {
                uint32_t v = 0;
                #pragma unroll
                for (int j = 0; j < 2; j++) {
                    int k = ch * 128 + ks * 16 + (lane & 3) * 2 + j + e * 8;
                    __half h = __float2half_rn(w_out[col * 256 + k]);
                    v |= (uint32_t)(*(uint16_t*)&h) << (16 * j);
                }
                pk[e] = v;
            }
            w = make_uint2(pk[0], pk[1]);
        }
        g_wof[idx] = w;
    }
    if (idx < 1024) {
        int ntile = idx >> 6, c = idx & 63;
        int srow = col2row(ntile, c);
        g_b1p[idx] = b_ih1[srow] + b_hh1[srow];
    }
    if (idx < 8) g_barm[idx] = 0;
}

__global__ void prep_init(const float* __restrict__ latent,
                          const float* __restrict__ w_lh, const float* __restrict__ b_lh,
                          const float* __restrict__ w_lc, const float* __restrict__ b_lc,
                          const float* __restrict__ w_ih0, const float* __restrict__ b_ih0,
                          const float* __restrict__ b_hh0) {
    __shared__ float lat[LATD];
    const int b = blockIdx.x, t = threadIdx.x;
    if (t < LATD) lat[t] = latent[b * LATD + t];
    __syncthreads();

    #pragma unroll
    for (int g = 0; g < 4; g++) {
        int n = g * 256 + t;
        const float4* wr = (const float4*)(w_ih0 + n * LATD);
        float acc = b_ih0[n] + b_hh0[n];
        #pragma unroll 8
        for (int q = 0; q < LATD / 4; q++) {
            float4 w4 = __ldg(wr + q);
            acc += lat[4*q]*w4.x + lat[4*q+1]*w4.y + lat[4*q+2]*w4.z + lat[4*q+3]*w4.w;
        }
        int colp = (t >> 4) * 64 + (g >> 1) * 32 + ((t >> 2) & 3) * 8 + (t & 3) * 2 + (g & 1);
        g_gx0p[b * 1024 + colp] = acc;
    }
    #pragma unroll
    for (int half = 0; half < 2; half++) {
        float hv, cv;
        {
            const float4* wr = (const float4*)(w_lh + (half * 256 + t) * LATD);
            float acc = b_lh[half * 256 + t];
            #pragma unroll 8
            for (int q = 0; q < LATD / 4; q++) {
                float4 w4 = __ldg(wr + q);
                acc += lat[4*q]*w4.x + lat[4*q+1]*w4.y + lat[4*q+2]*w4.z + lat[4*q+3]*w4.w;
            }
            hv = acc;
        }
        {
            const float4* wr = (const float4*)(w_lc + (half * 256 + t) * LATD);
            float acc = b_lc[half * 256 + t];
            #pragma unroll 8
            for (int q = 0; q < LATD / 4; q++) {
                float4 w4 = __ldg(wr + q);
                acc += lat[4*q]*w4.x + lat[4*q+1]*w4.y + lat[4*q+2]*w4.z + lat[4*q+3]*w4.w;
            }
            cv = acc;
        }
        int p = HB + b * 256 + t;                    // h(-1) -> buffer 1
        if (half == 0) g_h0f[p] = __float2half_rn(hv);
        else           g_h1f[p] = __float2half_rn(hv);
        g_cinit[b * 512 + half * 256 + t] = cv;
    }
}

// ================= main kernel pieces =================
// per-mtile barrier (16 CTAs), release-arrive / acquire-poll (no MEMBAR)
__device__ __forceinline__ void gbarm(int tid, int mtile, unsigned target) {
    __syncthreads();
    if (tid == 0) {
        unsigned v;
        asm volatile("atom.release.gpu.global.add.u32 %0, [%1], 1;"
                     : "=r"(v) : "l"(&g_barm[mtile]) : "memory");
        while (v + 1 < target) {
            asm volatile("ld.acquire.gpu.global.u32 %0, [%1];"
                         : "=r"(v) : "l"(&g_barm[mtile]) : "memory");
        }
    }
    __syncthreads();
}

// async-copy one 128x128 fp16 chunk into XOR-swizzled 256B-stride A tile (256 thr)
__device__ __forceinline__ void fill_async(uint32_t sdst, const __half* src, int kofs, int tid) {
    const uint4* s4 = (const uint4*)(src + kofs);    // row stride 512B = 32 uint4
    #pragma unroll
    for (int it = 0; it < 8; it++) {
        int i = tid + it * 256;
        int r = i >> 4, seg = i & 15;
        cpa16(sdst + r * 256 + ((seg ^ (r & 7)) << 4), s4 + r * 32 + seg);
    }
}

// one GEMM pass over a K=128 chunk: 8 k-steps x 8 n-tiles (fp16)
__device__ __forceinline__ void gemm_pass(uint32_t at_warp, uint32_t wf, float acc[8][4], int lane) {
    #pragma unroll
    for (int ks = 0; ks < 8; ks++) {
        uint32_t a0, a1, a2, a3;
        uint32_t row = lane & 15;
        uint32_t seg = (uint32_t)(ks * 2) + (uint32_t)(lane >> 4);
        uint32_t aaddr = at_warp + row * 256 + ((seg ^ (row & 7)) << 4);
        asm volatile("ldmatrix.sync.aligned.m8n8.x4.shared.b16 {%0,%1,%2,%3}, [%4];"
                     : "=r"(a0), "=r"(a1), "=r"(a2), "=r"(a3) : "r"(aaddr));
        #pragma unroll
        for (int nt = 0; nt < 8; nt++) {
            uint32_t b0, b1;
            uint32_t baddr = wf + ((ks * 8 + nt) * 32 + lane) * 8;
            asm volatile("ld.shared.v2.u32 {%0,%1}, [%2];" : "=r"(b0), "=r"(b1) : "r"(baddr));
            asm volatile(
                "mma.sync.aligned.m16n8k16.row.col.f32.f16.f16.f32 "
                "{%0,%1,%2,%3}, {%4,%5,%6,%7}, {%8,%9}, {%0,%1,%2,%3};"
                : "+f"(acc[nt][0]), "+f"(acc[nt][1]), "+f"(acc[nt][2]), "+f"(acc[nt][3])
                : "r"(a0), "r"(a1), "r"(a2), "r"(a3), "r"(b0), "r"(b1));
        }
    }
}

// out projection for this CTA's 4 cols from the Q tile
__device__ __forceinline__ void outproj(uint32_t Qw0, uint32_t Qw1, const uint2* wofp,
                                        float bo0, float bo1, float* __restrict__ out,
                                        int so, int rbase, int ntile, int lane) {
    float oa[4] = {0.f, 0.f, 0.f, 0.f};
    #pragma unroll
    for (int ch = 0; ch < 2; ch++) {
        uint32_t qb = ch ? Qw1 : Qw0;
        #pragma unroll
        for (int ks = 0; ks < 8; ks++) {
            uint32_t a0, a1, a2, a3;
            uint32_t row = lane & 15;
            uint32_t seg = (uint32_t)(ks * 2) + (uint32_t)(lane >> 4);
            uint32_t aaddr = qb + row * 256 + ((seg ^ (row & 7)) << 4);
            asm volatile("ldmatrix.sync.aligned.m8n8.x4.shared.b16 {%0,%1,%2,%3}, [%4];"
                         : "=r"(a0), "=r"(a1), "=r"(a2), "=r"(a3) : "r"(aaddr));
            uint2 bb = __ldg(wofp + ch * 256 + ks * 32);
            asm volatile(
                "mma.sync.aligned.m16n8k16.row.col.f32.f16.f16.f32 "
                "{%0,%1,%2,%3}, {%4,%5,%6,%7}, {%8,%9}, {%0,%1,%2,%3};"
                : "+f"(oa[0]), "+f"(oa[1]), "+f"(oa[2]), "+f"(oa[3])
                : "r"(a0), "r"(a1), "r"(a2), "r"(a3), "r"(bb.x), "r"(bb.y));
        }
    }
    if ((lane & 3) < 2) {
        int co = ntile * 4 + 2 * (lane & 3);
        float2 v0 = make_float2(oa[0] + bo0, oa[1] + bo1);
        float2 v1 = make_float2(oa[2] + bo0, oa[3] + bo1);
        *(float2*)&out[(rbase * TT + so) * OUTD + co] = v0;
        *(float2*)&out[((rbase + 8) * TT + so) * OUTD + co] = v1;
    }
}

__device__ __forceinline__ void cell_pub(float acc[8][4], float* c,
                                         __half* gh, int rbase, int ntile, int lane) {
    #pragma unroll
    for (int nt_ = 0; nt_ < 4; nt_++) {
        #pragma unroll
        for (int rh = 0; rh < 2; rh++) {
            int i = nt_ * 2 + rh;
            float gi = acc[nt_][rh * 2],     gf = acc[nt_][rh * 2 + 1];
            float gg = acc[nt_ + 4][rh * 2], go = acc[nt_ + 4][rh * 2 + 1];
            float cn = sigf(gf) * c[i] + sigf(gi) * tanhf_(gg);
            c[i] = cn;
            float h = sigf(go) * tanhf_(cn);
            int rowg = rbase + rh * 8;
            int ug = ntile * 16 + nt_ * 4 + (lane & 3);
            stg16(gh + rowg * 256 + ug, __float2half_rn(h));
        }
    }
}

__global__ void __launch_bounds__(256, 1)
lstm_mma(const float* __restrict__ b_out, float* __restrict__ out) {
    extern __shared__ char smem[];
    const int tid = threadIdx.x, wid = tid >> 5, lane = tid & 31;
    const int mtile = blockIdx.x >> 4, ntile = blockIdx.x & 15;
    const uint32_t sbase = s2u(smem);
    const uint32_t P = sbase + SM_P, Q = sbase + SM_Q;
    const uint32_t Pw0 = P + wid * 4096, Pw1 = P + 32768 + wid * 4096;
    const uint32_t Qw0 = Q + wid * 4096, Qw1 = Q + 32768 + wid * 4096;
    const int rbase = mtile * 128 + wid * 16 + (lane >> 2);
    const int hoff = mtile * 128 * 256;

    // weight fragments -> SMEM
    {
        const uint4* sh = (const uint4*)(g_wf + ntile * 24576);
        uint4* dh = (uint4*)(smem + SM_WF);
        for (int i = tid; i < 6144; i += 256) dh[i] = __ldg(sh + i);
    }

    // per-lane constants
    float gx[8][4], b1r[8][2];
    #pragma unroll
    for (int nt = 0; nt < 8; nt++) {
        #pragma unroll
        for (int r = 0; r < 4; r++) {
            int rowg = rbase + (r >> 1) * 8;
            int c = nt * 8 + 2 * (lane & 3) + (r & 1);
            gx[nt][r] = __ldg(&g_gx0p[rowg * 1024 + ntile * 64 + c]);
        }
        b1r[nt][0] = __ldg(&g_b1p[ntile * 64 + nt * 8 + 2 * (lane & 3)]);
        b1r[nt][1] = __ldg(&g_b1p[ntile * 64 + nt * 8 + 2 * (lane & 3) + 1]);
    }
    float c0[8], c1[8];
    #pragma unroll
    for (int i = 0; i < 8; i++) {
        int rowg = rbase + (i & 1) * 8;
        int ug = ntile * 16 + (i >> 1) * 4 + (lane & 3);
        c0[i] = __ldg(&g_cinit[rowg * 512 + ug]);
        c1[i] = __ldg(&g_cinit[rowg * 512 + 256 + ug]);
    }
    float bo0 = 0.f, bo1 = 0.f;
    if ((lane & 3) < 2) {
        bo0 = __ldg(&b_out[ntile * 4 + 2 * (lane & 3)]);
        bo1 = __ldg(&b_out[ntile * 4 + 2 * (lane & 3) + 1]);
    }
    const uint2* wofp = g_wof + ntile * 512 + lane;
    __syncthreads();

    unsigned tgt = 16;
    float acc0[8][4], acc1[8][4];

    // ======== layer-skewed pipeline: phase p = L0(step p) + L1(step p-1) ========
    #pragma unroll 1
    for (int p = 0; p <= TT; p++) {
        const int rb0 = (p + 1) & 1;     // h0(p-1) buffer
        const int rb1 = p & 1;           // h1(p-2) buffer

        // group 1: Q <- h1(p-2); group 0: P <- h0(p-1)
        if (p >= 1) {
            fill_async(Q,         g_h1f + rb1 * HB + hoff, 0,   tid);
            fill_async(Q + 32768, g_h1f + rb1 * HB + hoff, 128, tid);
        }
        CP_COMMIT();
        fill_async(P,         g_h0f + rb0 * HB + hoff, 0,   tid);
        fill_async(P + 32768, g_h0f + rb0 * HB + hoff, 128, tid);
        CP_COMMIT();

        if (p >= 1) {
            CP_WAIT1();                  // Q ready (P may still fly)
            __syncthreads();
            // L1(p-1): W1b part on Q
            #pragma unroll
            for (int nt = 0; nt < 8; nt++) {
                acc1[nt][0] = b1r[nt][0]; acc1[nt][1] = b1r[nt][1];
                acc1[nt][2] = b1r[nt][0]; acc1[nt][3] = b1r[nt][1];
            }
            gemm_pass(Qw0, sbase + SM_WF + 4 * 16384, acc1, lane);
            gemm_pass(Qw1, sbase + SM_WF + 5 * 16384, acc1, lane);
            if (p >= 2)                  // outproj for step p-2 (Q = h1(p-2))
                outproj(Qw0, Qw1, wofp, bo0, bo1, out, p - 2, rbase, ntile, lane);
        }

        CP_WAIT0();                      // P ready
        __syncthreads();

        if (p <= TT - 1) {
            // L0(p) on P
            #pragma unroll
            for (int nt = 0; nt < 8; nt++)
                #pragma unroll
                for (int r = 0; r < 4; r++) acc0[nt][r] = gx[nt][r];
            gemm_pass(Pw0, sbase + SM_WF + 0 * 16384, acc0, lane);
            gemm_pass(Pw1, sbase + SM_WF + 1 * 16384, acc0, lane);
            cell_pub(acc0, c0, g_h0f + (p & 1) * HB, rbase, ntile, lane);   // h0(p)
        }
        if (p >= 1) {
            // L1(p-1): W1a part on P (same h0(p-1) tile)
            gemm_pass(Pw0, sbase + SM_WF + 2 * 16384, acc1, lane);
            gemm_pass(Pw1, sbase + SM_WF + 3 * 16384, acc1, lane);
            cell_pub(acc1, c1, g_h1f + ((p - 1) & 1) * HB, rbase, ntile, lane); // h1(p-1)
        }

        gbarm(tid, mtile, tgt); tgt += 16;   // single barrier per phase
    }

    // epilogue: outproj(TT-1); h1(TT-1) in buffer (TT-1)&1 = 1
    fill_async(Q,         g_h1f + HB + hoff, 0,   tid);
    fill_async(Q + 32768, g_h1f + HB + hoff, 128, tid);
    CP_COMMIT();
    CP_WAIT0();
    __syncthreads();
    outproj(Qw0, Qw1, wofp, bo0, bo1, out, TT - 1, rbase, ntile, lane);
}

// ================= launch =================
extern "C" void kernel_launch(void* const* d_in, const int* in_sizes, int n_in,
                              void* d_out, int out_size) {
    const float* latent = (const float*)d_in[0];
    const float* w_lh   = (const float*)d_in[1];
    const float* b_lh   = (const float*)d_in[2];
    const float* w_lc   = (const float*)d_in[3];
    const float* b_lc   = (const float*)d_in[4];
    const float* w_ih0  = (const float*)d_in[5];
    const float* w_hh0  = (const float*)d_in[6];
    const float* b_ih0  = (const float*)d_in[7];
    const float* b_hh0  = (const float*)d_in[8];
    const float* w_ih1  = (const float*)d_in[9];
    const float* w_hh1  = (const float*)d_in[10];
    const float* b_ih1  = (const float*)d_in[11];
    const float* b_hh1  = (const float*)d_in[12];
    const float* w_out  = (const float*)d_in[13];
    const float* b_out  = (const float*)d_in[14];
    float* out = (float*)d_out;

    cudaFuncSetAttribute(lstm_mma, cudaFuncAttributeMaxDynamicSharedMemorySize, SMEM_SZ);

    prep_wfrag<<<1536, 256>>>(w_hh0, w_ih1, w_hh1);
    prep_misc<<<64, 256>>>(w_out, b_ih1, b_hh1);
    prep_init<<<BATCH, 256>>>(latent, w_lh, b_lh, w_lc, b_lc, w_ih0, b_ih0, b_hh0);
    lstm_mma<<<128, 256, SMEM_SZ>>>(b_out, out);
}